// round 2
// baseline (speedup 1.0000x reference)
#include <cuda_runtime.h>
#include <math.h>

// ---------------------------------------------------------------------------
// Problem constants (shapes are fixed by the reference)
// ---------------------------------------------------------------------------
#define NNODES 50000
#define NEDGES 800000
// feature widths: layers 0/1: H=4, C=32 (HC=128); layer 2: H=1, C=64

// ---------------------------------------------------------------------------
// Scratch (no cudaMalloc allowed -> __device__ globals)
// ---------------------------------------------------------------------------
__device__ float g_xl[NNODES * 128];
__device__ float g_xr[NNODES * 128];
__device__ float g_h[NNODES * 128];     // layer input (post-ELU)
__device__ float g_acc[NNODES * 128];   // layer accumulator (residual + messages)
__device__ float g_logit[NEDGES * 4];   // per-edge logits, overwritten with p
__device__ float g_m[NNODES * 4];       // segment max
__device__ float g_den[NNODES * 4];     // segment sum
__device__ int   g_src[NEDGES];
__device__ int   g_dst[NEDGES];
__device__ int   g_is64;

// ---------------------------------------------------------------------------
// Helpers
// ---------------------------------------------------------------------------
__device__ __forceinline__ void atomicMaxF(float* addr, float v) {
    // sign-split trick: works for mixed-sign floats, init must be -inf
    if (v >= 0.0f)
        atomicMax((int*)addr, __float_as_int(v));
    else
        atomicMin((unsigned int*)addr, __float_as_uint(v));
}

// ---------------------------------------------------------------------------
// Edge index decode (int64 vs int32 detection, done on-device each call)
// ---------------------------------------------------------------------------
__global__ void detect_kernel(const void* ei) {
    if (threadIdx.x == 0 && blockIdx.x == 0) {
        const long long* p = (const long long*)ei;
        int ok = 1;
        for (int i = 0; i < 64; i++) {
            long long v = p[i];
            if (v < 0 || v >= NNODES) { ok = 0; break; }
        }
        g_is64 = ok;
    }
}

__global__ void decode_kernel(const void* ei, int E) {
    int i = blockIdx.x * blockDim.x + threadIdx.x;
    if (i >= E) return;
    if (g_is64) {
        const long long* p = (const long long*)ei;
        g_src[i] = (int)p[i];
        g_dst[i] = (int)p[(size_t)E + i];
    } else {
        const int* p = (const int*)ei;
        g_src[i] = p[i];
        g_dst[i] = p[E + i];
    }
}

// ---------------------------------------------------------------------------
// GEMM: C[nrows, NCOLS] = A[nrows, 128] @ B[128, NCOLS] + bias[NCOLS]
// Block: 64 rows x NCOLS cols, 256 threads (8 warps x 8 rows, lane covers cols)
// ---------------------------------------------------------------------------
template <int NCOLS>
__global__ void gemm_bias_kernel(const float* __restrict__ A,
                                 const float* __restrict__ B,
                                 const float* __restrict__ bias,
                                 float* __restrict__ C, int nrows) {
    __shared__ float As[64][128];
    const int tid  = threadIdx.x;
    const int lane = tid & 31;
    const int warp = tid >> 5;
    const int row0 = blockIdx.x * 64;

    // cooperative load of the A tile (zero-padded at the tail)
    #pragma unroll
    for (int i = 0; i < 32; i++) {
        int idx = i * 256 + tid;
        int r = idx >> 7, c = idx & 127;
        int gr = row0 + r;
        As[r][c] = (gr < nrows) ? A[(size_t)gr * 128 + c] : 0.0f;
    }
    __syncthreads();

    constexpr int CPL = NCOLS / 32;   // cols per lane
    const int colb = lane * CPL;
    float acc[8][CPL];
    #pragma unroll
    for (int r = 0; r < 8; r++)
        #pragma unroll
        for (int j = 0; j < CPL; j++) acc[r][j] = 0.0f;

    #pragma unroll 4
    for (int k = 0; k < 128; k++) {
        float b[CPL];
        #pragma unroll
        for (int j = 0; j < CPL; j++) b[j] = B[k * NCOLS + colb + j];
        #pragma unroll
        for (int r = 0; r < 8; r++) {
            float a = As[warp * 8 + r][k];
            #pragma unroll
            for (int j = 0; j < CPL; j++) acc[r][j] += a * b[j];
        }
    }

    #pragma unroll
    for (int r = 0; r < 8; r++) {
        int gr = row0 + warp * 8 + r;
        if (gr < nrows) {
            #pragma unroll
            for (int j = 0; j < CPL; j++)
                C[(size_t)gr * NCOLS + colb + j] = acc[r][j] + bias[colb + j];
        }
    }
}

// ---------------------------------------------------------------------------
// Edge pass A: logits + segment max.  One warp per edge.
// ---------------------------------------------------------------------------
template <int H, int C>
__global__ void edge_logit_kernel(const float* __restrict__ xl,
                                  const float* __restrict__ xr,
                                  const float* __restrict__ att,
                                  float* __restrict__ logit,
                                  float* __restrict__ m, int E) {
    const int w = (blockIdx.x * blockDim.x + threadIdx.x) >> 5;
    if (w >= E) return;
    const int lane = threadIdx.x & 31;
    constexpr int HC = H * C;
    constexpr int R  = HC / 32;   // elems per lane (4 or 2)
    constexpr int L  = 32 / H;    // lanes per head

    const int s = g_src[w], d = g_dst[w];
    const float* pl = xl + (size_t)s * HC + lane * R;
    const float* pr = xr + (size_t)d * HC + lane * R;
    const float* pa = att + lane * R;

    float sum = 0.0f;
    if (R == 4) {
        float4 a = *(const float4*)pl;
        float4 b = *(const float4*)pr;
        float4 t = *(const float4*)pa;
        float v;
        v = a.x + b.x; v = v > 0.0f ? v : 0.2f * v; sum += v * t.x;
        v = a.y + b.y; v = v > 0.0f ? v : 0.2f * v; sum += v * t.y;
        v = a.z + b.z; v = v > 0.0f ? v : 0.2f * v; sum += v * t.z;
        v = a.w + b.w; v = v > 0.0f ? v : 0.2f * v; sum += v * t.w;
    } else {
        float2 a = *(const float2*)pl;
        float2 b = *(const float2*)pr;
        float2 t = *(const float2*)pa;
        float v;
        v = a.x + b.x; v = v > 0.0f ? v : 0.2f * v; sum += v * t.x;
        v = a.y + b.y; v = v > 0.0f ? v : 0.2f * v; sum += v * t.y;
    }
    #pragma unroll
    for (int off = L >> 1; off; off >>= 1)
        sum += __shfl_xor_sync(0xffffffffu, sum, off);

    if ((lane & (L - 1)) == 0) {
        int h = lane / L;
        logit[(size_t)w * H + h] = sum;
        atomicMaxF(&m[d * H + h], sum);
    }
}

// ---------------------------------------------------------------------------
// Edge pass B: p = exp(logit - m[dst]); denom += p.  One thread per (edge, head)
// ---------------------------------------------------------------------------
template <int H>
__global__ void edge_softmax_kernel(float* __restrict__ logit,
                                    const float* __restrict__ m,
                                    float* __restrict__ den, int E) {
    int i = blockIdx.x * blockDim.x + threadIdx.x;
    if (i >= E * H) return;
    int e = i / H, h = i - e * H;
    int d = g_dst[e];
    float p = __expf(logit[i] - m[d * H + h]);
    logit[i] = p;
    atomicAdd(&den[d * H + h], p);
}

// ---------------------------------------------------------------------------
// Edge pass C: out[dst] += xl[src] * alpha.  One warp per edge.
// ---------------------------------------------------------------------------
template <int H, int C>
__global__ void edge_aggregate_kernel(const float* __restrict__ xl,
                                      const float* __restrict__ p,
                                      const float* __restrict__ den,
                                      float* __restrict__ out, int E) {
    const int w = (blockIdx.x * blockDim.x + threadIdx.x) >> 5;
    if (w >= E) return;
    const int lane = threadIdx.x & 31;
    constexpr int HC = H * C;
    constexpr int R  = HC / 32;
    constexpr int L  = 32 / H;

    const int s = g_src[w], d = g_dst[w];
    const int h = lane / L;
    float alpha = p[(size_t)w * H + h] / (den[d * H + h] + 1e-16f);

    const float* pl = xl + (size_t)s * HC + lane * R;
    float* po = out + (size_t)d * HC + lane * R;
    if (R == 4) {
        float4 a = *(const float4*)pl;
        atomicAdd(po + 0, a.x * alpha);
        atomicAdd(po + 1, a.y * alpha);
        atomicAdd(po + 2, a.z * alpha);
        atomicAdd(po + 3, a.w * alpha);
    } else {
        float2 a = *(const float2*)pl;
        atomicAdd(po + 0, a.x * alpha);
        atomicAdd(po + 1, a.y * alpha);
    }
}

// ---------------------------------------------------------------------------
// Small elementwise kernels
// ---------------------------------------------------------------------------
__global__ void init_md_kernel(float* m, float* den, int n) {
    int i = blockIdx.x * blockDim.x + threadIdx.x;
    if (i < n) { m[i] = __int_as_float(0xff800000); den[i] = 0.0f; }  // -inf, 0
}

__global__ void init_out_bias_kernel(float* out, const float* __restrict__ bias,
                                     int n, int ncol) {
    int i = blockIdx.x * blockDim.x + threadIdx.x;
    if (i < n) out[i] = bias[i % ncol];
}

__global__ void elu_kernel(const float* __restrict__ in, float* __restrict__ out, int n) {
    int i = blockIdx.x * blockDim.x + threadIdx.x;
    if (i < n) {
        float v = in[i];
        out[i] = v > 0.0f ? v : (__expf(v) - 1.0f);
    }
}

// ---------------------------------------------------------------------------
// Launch
// ---------------------------------------------------------------------------
extern "C" void kernel_launch(void* const* d_in, const int* in_sizes, int n_in,
                              void* d_out, int out_size) {
    const float* x    = (const float*)d_in[0];
    const void*  ei   = d_in[1];
    const float* Wl0  = (const float*)d_in[2];
    const float* bl0  = (const float*)d_in[3];
    const float* Wr0  = (const float*)d_in[4];
    const float* br0  = (const float*)d_in[5];
    const float* att0 = (const float*)d_in[6];
    const float* b0   = (const float*)d_in[7];
    const float* res0 = (const float*)d_in[8];
    const float* Wl1  = (const float*)d_in[9];
    const float* bl1  = (const float*)d_in[10];
    const float* Wr1  = (const float*)d_in[11];
    const float* br1  = (const float*)d_in[12];
    const float* att1 = (const float*)d_in[13];
    const float* b1   = (const float*)d_in[14];
    const float* res1 = (const float*)d_in[15];
    const float* Wl2  = (const float*)d_in[16];
    const float* bl2  = (const float*)d_in[17];
    const float* Wr2  = (const float*)d_in[18];
    const float* br2  = (const float*)d_in[19];
    const float* att2 = (const float*)d_in[20];
    const float* b2   = (const float*)d_in[21];
    float* out = (float*)d_out;

    const int N = in_sizes[0] / 128;        // 50000
    const int E = in_sizes[1] / 2;          // 800000

    float *p_xl, *p_xr, *p_h, *p_acc, *p_logit, *p_m, *p_den;
    cudaGetSymbolAddress((void**)&p_xl,    g_xl);
    cudaGetSymbolAddress((void**)&p_xr,    g_xr);
    cudaGetSymbolAddress((void**)&p_h,     g_h);
    cudaGetSymbolAddress((void**)&p_acc,   g_acc);
    cudaGetSymbolAddress((void**)&p_logit, g_logit);
    cudaGetSymbolAddress((void**)&p_m,     g_m);
    cudaGetSymbolAddress((void**)&p_den,   g_den);

    const int TB = 256;
    const int gemm_blocks = (N + 63) / 64;
    const int edge_warp_blocks = (E + 7) / 8;   // 8 warps (edges) per block

    // decode edge index (int64 vs int32 robust)
    detect_kernel<<<1, 32>>>(ei);
    decode_kernel<<<(E + TB - 1) / TB, TB>>>(ei, E);

    // ------------------- layer 0: 128 -> 4x32, residual -------------------
    gemm_bias_kernel<128><<<gemm_blocks, TB>>>(x, Wl0, bl0, p_xl, N);
    gemm_bias_kernel<128><<<gemm_blocks, TB>>>(x, Wr0, br0, p_xr, N);
    gemm_bias_kernel<128><<<gemm_blocks, TB>>>(x, res0, b0, p_acc, N);
    init_md_kernel<<<(N * 4 + TB - 1) / TB, TB>>>(p_m, p_den, N * 4);
    edge_logit_kernel<4, 32><<<edge_warp_blocks, TB>>>(p_xl, p_xr, att0, p_logit, p_m, E);
    edge_softmax_kernel<4><<<(E * 4 + TB - 1) / TB, TB>>>(p_logit, p_m, p_den, E);
    edge_aggregate_kernel<4, 32><<<edge_warp_blocks, TB>>>(p_xl, p_logit, p_den, p_acc, E);
    elu_kernel<<<(N * 128 + TB - 1) / TB, TB>>>(p_acc, p_h, N * 128);

    // ------------------- layer 1: 128 -> 4x32, residual -------------------
    gemm_bias_kernel<128><<<gemm_blocks, TB>>>(p_h, Wl1, bl1, p_xl, N);
    gemm_bias_kernel<128><<<gemm_blocks, TB>>>(p_h, Wr1, br1, p_xr, N);
    gemm_bias_kernel<128><<<gemm_blocks, TB>>>(p_h, res1, b1, p_acc, N);
    init_md_kernel<<<(N * 4 + TB - 1) / TB, TB>>>(p_m, p_den, N * 4);
    edge_logit_kernel<4, 32><<<edge_warp_blocks, TB>>>(p_xl, p_xr, att1, p_logit, p_m, E);
    edge_softmax_kernel<4><<<(E * 4 + TB - 1) / TB, TB>>>(p_logit, p_m, p_den, E);
    edge_aggregate_kernel<4, 32><<<edge_warp_blocks, TB>>>(p_xl, p_logit, p_den, p_acc, E);
    elu_kernel<<<(N * 128 + TB - 1) / TB, TB>>>(p_acc, p_h, N * 128);

    // ------------------- layer 2: 128 -> 64, heads=1, no residual ----------
    gemm_bias_kernel<64><<<gemm_blocks, TB>>>(p_h, Wl2, bl2, p_xl, N);
    gemm_bias_kernel<64><<<gemm_blocks, TB>>>(p_h, Wr2, br2, p_xr, N);
    init_out_bias_kernel<<<(N * 64 + TB - 1) / TB, TB>>>(out, b2, N * 64, 64);
    init_md_kernel<<<(N + TB - 1) / TB, TB>>>(p_m, p_den, N);
    edge_logit_kernel<1, 64><<<edge_warp_blocks, TB>>>(p_xl, p_xr, att2, p_logit, p_m, E);
    edge_softmax_kernel<1><<<(E + TB - 1) / TB, TB>>>(p_logit, p_m, p_den, E);
    edge_aggregate_kernel<1, 64><<<edge_warp_blocks, TB>>>(p_xl, p_logit, p_den, out, E);
}

// round 3
// speedup vs baseline: 2.3712x; 2.3712x over previous
#include <cuda_runtime.h>
#include <math.h>

#define NNODES 50000
#define NEDGES 800000

// ---------------------------------------------------------------------------
// Scratch (__device__ globals; no cudaMalloc allowed)
// ---------------------------------------------------------------------------
__device__ float g_xl[NNODES * 128];
__device__ float g_xr[NNODES * 128];
__device__ float g_h[NNODES * 128];      // layer input (post-ELU)
__device__ float g_acc[NNODES * 128];    // residual accumulator (A@res + b)
__device__ int   g_src[NEDGES];
__device__ int   g_dst[NEDGES];
__device__ int   g_srcSorted[NEDGES];    // src ids grouped by dst (CSR)
__device__ int   g_deg[NNODES];
__device__ int   g_cnt[NNODES];
__device__ int   g_rowptr[NNODES + 1];
__device__ int   g_is64;

// ---------------------------------------------------------------------------
// Edge index decode (int64 vs int32 robust) + degree histogram
// ---------------------------------------------------------------------------
__global__ void detect_kernel(const void* ei) {
    if (threadIdx.x == 0 && blockIdx.x == 0) {
        const long long* p = (const long long*)ei;
        int ok = 1;
        for (int i = 0; i < 64; i++) {
            long long v = p[i];
            if (v < 0 || v >= NNODES) { ok = 0; break; }
        }
        g_is64 = ok;
    }
}

__global__ void decode_hist_kernel(const void* ei, int E) {
    int i = blockIdx.x * blockDim.x + threadIdx.x;
    if (i >= E) return;
    int s, d;
    if (g_is64) {
        const long long* p = (const long long*)ei;
        s = (int)p[i];
        d = (int)p[(size_t)E + i];
    } else {
        const int* p = (const int*)ei;
        s = p[i];
        d = p[E + i];
    }
    g_src[i] = s;
    g_dst[i] = d;
    atomicAdd(&g_deg[d], 1);
}

// single-block exclusive scan over N degrees -> rowptr[0..N]
__global__ void scan_kernel(int n) {
    __shared__ int ssum[1024];
    const int tid = threadIdx.x;
    const int chunk = (n + 1023) >> 10;
    const int b = tid * chunk;
    const int e = min(b + chunk, n);
    int s = 0;
    for (int i = b; i < e; i++) s += g_deg[i];
    ssum[tid] = s;
    __syncthreads();
    for (int off = 1; off < 1024; off <<= 1) {
        int v = (tid >= off) ? ssum[tid - off] : 0;
        __syncthreads();
        ssum[tid] += v;
        __syncthreads();
    }
    int run = (tid > 0) ? ssum[tid - 1] : 0;
    for (int i = b; i < e; i++) { g_rowptr[i] = run; run += g_deg[i]; }
    if (tid == 0) g_rowptr[n] = ssum[1023];
}

__global__ void scatter_kernel(int E) {
    int i = blockIdx.x * blockDim.x + threadIdx.x;
    if (i >= E) return;
    int d = g_dst[i];
    int pos = g_rowptr[d] + atomicAdd(&g_cnt[d], 1);
    g_srcSorted[pos] = g_src[i];
}

// ---------------------------------------------------------------------------
// Fused triple GEMM (same A): C_i = A[nrows,128] @ B_i[128,128] + bias_i
// 64 rows per CTA, 256 threads, B staged in smem (loaded once per CTA per mat)
// dynamic smem = 64*128 + 128*128 floats = 96KB
// ---------------------------------------------------------------------------
__global__ void gemm3_kernel(const float* __restrict__ A,
    const float* __restrict__ B0, const float* __restrict__ bias0, float* __restrict__ C0,
    const float* __restrict__ B1, const float* __restrict__ bias1, float* __restrict__ C1,
    const float* __restrict__ B2, const float* __restrict__ bias2, float* __restrict__ C2,
    int nrows)
{
    extern __shared__ float sm[];
    float* As = sm;               // 64 x 128
    float* Bs = sm + 64 * 128;    // 128 x 128
    const int tid = threadIdx.x, lane = tid & 31, warp = tid >> 5;
    const int row0 = blockIdx.x * 64;

    #pragma unroll
    for (int it = 0; it < 8; it++) {
        int idx4 = it * 256 + tid;          // float4 index into 64x128 tile
        int r = idx4 >> 5, c4 = idx4 & 31;
        int gr = row0 + r;
        float4 v = make_float4(0.f, 0.f, 0.f, 0.f);
        if (gr < nrows) v = *(const float4*)(A + (size_t)gr * 128 + c4 * 4);
        *(float4*)(As + r * 128 + c4 * 4) = v;
    }

    const float* Bm[3]    = {B0, B1, B2};
    const float* biasm[3] = {bias0, bias1, bias2};
    float*       Cm[3]    = {C0, C1, C2};
    const int colb = lane * 4;

    #pragma unroll 1
    for (int mat = 0; mat < 3; mat++) {
        __syncthreads();   // As ready (first iter) / previous compute done
        const float4* B4 = (const float4*)Bm[mat];
        #pragma unroll
        for (int it = 0; it < 16; it++) {
            int idx4 = it * 256 + tid;
            ((float4*)Bs)[idx4] = B4[idx4];
        }
        __syncthreads();

        float acc[8][4] = {};
        #pragma unroll 4
        for (int k = 0; k < 128; k++) {
            float4 b = *(const float4*)(Bs + k * 128 + colb);
            #pragma unroll
            for (int r = 0; r < 8; r++) {
                float a = As[(warp * 8 + r) * 128 + k];
                acc[r][0] += a * b.x; acc[r][1] += a * b.y;
                acc[r][2] += a * b.z; acc[r][3] += a * b.w;
            }
        }
        float4 bs4 = *(const float4*)(biasm[mat] + colb);
        float* C = Cm[mat];
        #pragma unroll
        for (int r = 0; r < 8; r++) {
            int gr = row0 + warp * 8 + r;
            if (gr < nrows) {
                float4 o = make_float4(acc[r][0] + bs4.x, acc[r][1] + bs4.y,
                                       acc[r][2] + bs4.z, acc[r][3] + bs4.w);
                *(float4*)(C + (size_t)gr * 128 + colb) = o;
            }
        }
    }
}

// Fused double GEMM, NCOLS=64 (layer 2). dynamic smem = 64KB
__global__ void gemm2_kernel(const float* __restrict__ A,
    const float* __restrict__ B0, const float* __restrict__ bias0, float* __restrict__ C0,
    const float* __restrict__ B1, const float* __restrict__ bias1, float* __restrict__ C1,
    int nrows)
{
    extern __shared__ float sm[];
    float* As = sm;               // 64 x 128
    float* Bs = sm + 64 * 128;    // 128 x 64
    const int tid = threadIdx.x, lane = tid & 31, warp = tid >> 5;
    const int row0 = blockIdx.x * 64;

    #pragma unroll
    for (int it = 0; it < 8; it++) {
        int idx4 = it * 256 + tid;
        int r = idx4 >> 5, c4 = idx4 & 31;
        int gr = row0 + r;
        float4 v = make_float4(0.f, 0.f, 0.f, 0.f);
        if (gr < nrows) v = *(const float4*)(A + (size_t)gr * 128 + c4 * 4);
        *(float4*)(As + r * 128 + c4 * 4) = v;
    }

    const float* Bm[2]    = {B0, B1};
    const float* biasm[2] = {bias0, bias1};
    float*       Cm[2]    = {C0, C1};
    const int colb = lane * 2;

    #pragma unroll 1
    for (int mat = 0; mat < 2; mat++) {
        __syncthreads();
        const float4* B4 = (const float4*)Bm[mat];
        #pragma unroll
        for (int it = 0; it < 8; it++) {
            int idx4 = it * 256 + tid;
            ((float4*)Bs)[idx4] = B4[idx4];
        }
        __syncthreads();

        float acc[8][2] = {};
        #pragma unroll 4
        for (int k = 0; k < 128; k++) {
            float2 b = *(const float2*)(Bs + k * 64 + colb);
            #pragma unroll
            for (int r = 0; r < 8; r++) {
                float a = As[(warp * 8 + r) * 128 + k];
                acc[r][0] += a * b.x; acc[r][1] += a * b.y;
            }
        }
        float2 bs2 = *(const float2*)(biasm[mat] + colb);
        float* C = Cm[mat];
        #pragma unroll
        for (int r = 0; r < 8; r++) {
            int gr = row0 + warp * 8 + r;
            if (gr < nrows) {
                float2 o = make_float2(acc[r][0] + bs2.x, acc[r][1] + bs2.y);
                *(float2*)(C + (size_t)gr * 64 + colb) = o;
            }
        }
    }
}

// ---------------------------------------------------------------------------
// Warp-per-node GATv2 aggregation with online softmax.
// RESELU=true : out = elu(res_acc[n] + msg)        (layers 0/1)
// RESELU=false: out = bias + msg                   (layer 2)
// ---------------------------------------------------------------------------
template <int H, int C, bool RESELU>
__global__ void gat_aggregate_kernel(const float* __restrict__ xl,
                                     const float* __restrict__ xr,
                                     const float* __restrict__ att,
                                     const float* __restrict__ extra,
                                     float* __restrict__ out, int N)
{
    constexpr int HC = H * C;
    constexpr int R  = HC / 32;       // features per lane
    constexpr int L  = 32 / H;        // lanes per head
    const int n = (blockIdx.x * blockDim.x + threadIdx.x) >> 5;
    if (n >= N) return;
    const int lane = threadIdx.x & 31;
    const int fo = lane * R;

    float xrv[R], attv[R], acc[R];
    #pragma unroll
    for (int j = 0; j < R; j++) {
        xrv[j]  = xr[(size_t)n * HC + fo + j];
        attv[j] = att[fo + j];
        acc[j]  = 0.0f;
    }
    float m   = __int_as_float(0xff800000);   // -inf
    float den = 0.0f;

    const int beg = g_rowptr[n], end = g_rowptr[n + 1];
    for (int i = beg; i < end; i++) {
        const int s = g_srcSorted[i];
        float a[R];
        if (R == 4) {
            float4 t = *(const float4*)(xl + (size_t)s * HC + fo);
            a[0] = t.x; a[1] = t.y; a[2] = t.z; a[3] = t.w;
        } else {
            float2 t = *(const float2*)(xl + (size_t)s * HC + fo);
            a[0] = t.x; a[1] = t.y;
        }
        float lg = 0.0f;
        #pragma unroll
        for (int j = 0; j < R; j++) {
            float v = a[j] + xrv[j];
            v = v > 0.0f ? v : 0.2f * v;
            lg += v * attv[j];
        }
        #pragma unroll
        for (int off = L >> 1; off; off >>= 1)
            lg += __shfl_xor_sync(0xffffffffu, lg, off);

        float mn = fmaxf(m, lg);
        float sc = __expf(m - mn);     // first iter: exp(-inf)=0
        float p  = __expf(lg - mn);
        den = den * sc + p;
        #pragma unroll
        for (int j = 0; j < R; j++) acc[j] = acc[j] * sc + p * a[j];
        m = mn;
    }

    const float inv = 1.0f / (den + 1e-16f);
    #pragma unroll
    for (int j = 0; j < R; j++) {
        float v = acc[j] * inv;
        if (RESELU) {
            v += extra[(size_t)n * HC + fo + j];
            v = v > 0.0f ? v : (__expf(v) - 1.0f);
        } else {
            v += extra[fo + j];
        }
        out[(size_t)n * HC + fo + j] = v;
    }
}

// ---------------------------------------------------------------------------
// Launch
// ---------------------------------------------------------------------------
extern "C" void kernel_launch(void* const* d_in, const int* in_sizes, int n_in,
                              void* d_out, int out_size) {
    const float* x    = (const float*)d_in[0];
    const void*  ei   = d_in[1];
    const float* Wl0  = (const float*)d_in[2];
    const float* bl0  = (const float*)d_in[3];
    const float* Wr0  = (const float*)d_in[4];
    const float* br0  = (const float*)d_in[5];
    const float* att0 = (const float*)d_in[6];
    const float* b0   = (const float*)d_in[7];
    const float* res0 = (const float*)d_in[8];
    const float* Wl1  = (const float*)d_in[9];
    const float* bl1  = (const float*)d_in[10];
    const float* Wr1  = (const float*)d_in[11];
    const float* br1  = (const float*)d_in[12];
    const float* att1 = (const float*)d_in[13];
    const float* b1   = (const float*)d_in[14];
    const float* res1 = (const float*)d_in[15];
    const float* Wl2  = (const float*)d_in[16];
    const float* bl2  = (const float*)d_in[17];
    const float* Wr2  = (const float*)d_in[18];
    const float* br2  = (const float*)d_in[19];
    const float* att2 = (const float*)d_in[20];
    const float* b2   = (const float*)d_in[21];
    float* out = (float*)d_out;

    const int N = in_sizes[0] / 128;
    const int E = in_sizes[1] / 2;

    float *p_xl, *p_xr, *p_h, *p_acc;
    int *p_deg, *p_cnt;
    cudaGetSymbolAddress((void**)&p_xl,  g_xl);
    cudaGetSymbolAddress((void**)&p_xr,  g_xr);
    cudaGetSymbolAddress((void**)&p_h,   g_h);
    cudaGetSymbolAddress((void**)&p_acc, g_acc);
    cudaGetSymbolAddress((void**)&p_deg, g_deg);
    cudaGetSymbolAddress((void**)&p_cnt, g_cnt);

    static bool attr_done = false;
    if (!attr_done) {
        cudaFuncSetAttribute(gemm3_kernel, cudaFuncAttributeMaxDynamicSharedMemorySize,
                             (64 * 128 + 128 * 128) * 4);
        cudaFuncSetAttribute(gemm2_kernel, cudaFuncAttributeMaxDynamicSharedMemorySize,
                             (64 * 128 + 128 * 64) * 4);
        attr_done = true;
    }

    const int TB = 256;
    const int gemm_blocks = (N + 63) / 64;
    const int node_blocks = (N + 7) / 8;      // warp per node, 8 warps/block
    const size_t sm3 = (64 * 128 + 128 * 128) * sizeof(float);
    const size_t sm2 = (64 * 128 + 128 * 64) * sizeof(float);

    // ---- CSR build (once per call) ----
    detect_kernel<<<1, 32>>>(ei);
    cudaMemsetAsync(p_deg, 0, (size_t)N * sizeof(int), 0);
    cudaMemsetAsync(p_cnt, 0, (size_t)N * sizeof(int), 0);
    decode_hist_kernel<<<(E + TB - 1) / TB, TB>>>(ei, E);
    scan_kernel<<<1, 1024>>>(N);
    scatter_kernel<<<(E + TB - 1) / TB, TB>>>(E);

    // ---- layer 0 ----
    gemm3_kernel<<<gemm_blocks, TB, sm3>>>(x, Wl0, bl0, p_xl, Wr0, br0, p_xr,
                                           res0, b0, p_acc, N);
    gat_aggregate_kernel<4, 32, true><<<node_blocks, TB>>>(p_xl, p_xr, att0,
                                                           p_acc, p_h, N);
    // ---- layer 1 ----
    gemm3_kernel<<<gemm_blocks, TB, sm3>>>(p_h, Wl1, bl1, p_xl, Wr1, br1, p_xr,
                                           res1, b1, p_acc, N);
    gat_aggregate_kernel<4, 32, true><<<node_blocks, TB>>>(p_xl, p_xr, att1,
                                                           p_acc, p_h, N);
    // ---- layer 2 ----
    gemm2_kernel<<<gemm_blocks, TB, sm2>>>(p_h, Wl2, bl2, p_xl, Wr2, br2, p_xr, N);
    gat_aggregate_kernel<1, 64, false><<<node_blocks, TB>>>(p_xl, p_xr, att2,
                                                            b2, out, N);
}